// round 7
// baseline (speedup 1.0000x reference)
#include <cuda_runtime.h>

#define NBOX 4096
#define T 512
#define PER 8                  // NBOX / T
#define NWARP 16               // T / 32
#define BMAX 32
#define THRESH 0.05f
#define FULL 0xffffffffu

// x1-sorted boxes + sorted-pos -> original index (L1-resident)
__device__ float4 g_sbox[NBOX];
__device__ int    g_orig[NBOX];

__device__ __forceinline__ int ld_acq(const int* p) {
    int v;
    asm volatile("ld.acquire.cta.b32 %0, [%1];" : "=r"(v) : "l"(p) : "memory");
    return v;
}
__device__ __forceinline__ void st_rel(int* p, int v) {
    asm volatile("st.release.cta.b32 [%0], %1;" :: "l"(p), "r"(v) : "memory");
}

__global__ __launch_bounds__(T, 1)
void softnms_kernel(const float4* __restrict__ boxes,
                    const float*  __restrict__ scores,
                    float* __restrict__ out, int out_size)
{
    __shared__ unsigned long long skv[NBOX];   // sort scratch
    __shared__ uint4   spoolA[NWARP];          // (m1,p1,m2,p2)
    __shared__ uint4   spoolB[NWARP];          // (m3,p3,m4val,-)
    __shared__ float4  sbatch_box[BMAX];
    __shared__ uint2   sbatch_meta[BMAX];      // (sorted pos, score bits)
    __shared__ int     spub;                   // members published (release)
    __shared__ int     sdone;                  // -1 scanning, else final B
    __shared__ int     sfro, sfpos;

    const int t    = threadIdx.x;
    const int lane = t & 31;
    const int wid  = t >> 5;

    // ---- init: zero score outputs, stage u64 sort keys ----
#pragma unroll
    for (int k = 0; k < PER; k++) {
        const int gi = t * PER + k;
        if (gi < out_size) out[gi] = 0.0f;
        skv[gi] = ((unsigned long long)__float_as_uint(boxes[gi].x) << 32)
                  | (unsigned)gi;
    }
    __syncthreads();

    // ---- bitonic sort ascending by x1 ----
    for (int k = 2; k <= NBOX; k <<= 1) {
        for (int j = k >> 1; j > 0; j >>= 1) {
#pragma unroll
            for (int e = t; e < NBOX; e += T) {
                const int ixj = e ^ j;
                if (ixj > e) {
                    const unsigned long long a = skv[e], c = skv[ixj];
                    const bool up = ((e & k) == 0);
                    if (up ? (a > c) : (a < c)) { skv[e] = c; skv[ixj] = a; }
                }
            }
            __syncthreads();
        }
    }

    // ---- load my PER sorted boxes; publish sorted tables ----
    float x1[PER], y1[PER], x2[PER], y2[PER], area[PER], s[PER];
    int   orig[PER];
    unsigned procm = 0;
    float tx2hi = 0.0f;
#pragma unroll
    for (int k = 0; k < PER; k++) {
        const int pos = t * PER + k;
        const int o   = (int)(unsigned)(skv[pos] & 0xffffffffu);
        orig[k] = o;
        const float4 b = boxes[o];
        x1[k] = b.x; y1[k] = b.y; x2[k] = b.z; y2[k] = b.w;
        area[k] = (b.z - b.x) * (b.w - b.y);
        s[k]    = scores[o];
        g_sbox[pos] = b;
        g_orig[pos] = o;
        tx2hi = fmaxf(tx2hi, b.z);
    }
    const float tx1lo = x1[0];
    __syncthreads();

    bool dirty = true;
    int  step  = 0;
    int  fro_final = 0, fpos_final = 0;

    while (step < NBOX) {
        // ============== rebuild per-warp top-3 (+4th value) ===============
        if (__ballot_sync(FULL, dirty)) {
            unsigned b1 = 0, b2 = 0, b3 = 0, b4 = 0;
            unsigned p1 = 0, p2 = 0, p3 = 0;
#pragma unroll
            for (int k = 0; k < PER; k++) {
                if (!((procm >> k) & 1u)) {
                    const unsigned ub = __float_as_uint(s[k]);   // scores > 0
                    const unsigned up = (unsigned)(t * PER + k);
                    if (ub > b1)      { b4=b3; b3=b2; p3=p2; b2=b1; p2=p1; b1=ub; p1=up; }
                    else if (ub > b2) { b4=b3; b3=b2; p3=p2; b2=ub; p2=up; }
                    else if (ub > b3) { b4=b3; b3=ub; p3=up; }
                    else if (ub > b4) { b4=ub; }
                }
            }
            unsigned wm[3], wq[3];
#pragma unroll
            for (int r = 0; r < 3; r++) {
                const unsigned m   = __reduce_max_sync(FULL, b1);
                const unsigned bal = __ballot_sync(FULL, b1 == m);
                const int src      = __ffs(bal) - 1;
                wm[r] = m;
                wq[r] = __shfl_sync(FULL, p1, src);
                if (lane == src) { b1=b2; p1=p2; b2=b3; p2=p3; b3=b4; b4=0; }
            }
            const unsigned m4 = __reduce_max_sync(FULL, b1);
            if (lane == 0) {
                spoolA[wid] = make_uint4(wm[0], wq[0], wm[1], wq[1]);
                spoolB[wid] = make_uint4(wm[2], wq[2], m4, 0u);
            }
            dirty = false;
        }
        if (t == 0) { spub = 0; sdone = -1; sfro = 0; }
        __syncthreads();   // bar1: pools + flags visible

        if (wid == 0) {
            // ============== producer: batch scan (decay-and-continue) ======
            unsigned k1=0, k2=0, k3=0, pp1=0, pp2=0, pp3=0, m4v=0;
            if (lane < NWARP) {
                const uint4 a = spoolA[lane], b = spoolB[lane];
                k1=a.x; pp1=a.y; k2=a.z; pp2=a.w; k3=b.x; pp3=b.y; m4v=b.z;
            }
            const unsigned M4 = __reduce_max_sync(FULL, m4v);
            float4 f1 = g_sbox[pp1]; const float a1 = (f1.z-f1.x)*(f1.w-f1.y);
            float4 f2 = g_sbox[pp2]; const float a2 = (f2.z-f2.x)*(f2.w-f2.y);
            float4 f3 = g_sbox[pp3]; const float a3 = (f3.z-f3.x)*(f3.w-f3.y);

            int B = 0, fz = 0; unsigned fp = 0;
            while (true) {
                const unsigned lk = (k1 > k2) ? ((k1 > k3) ? k1 : k3)
                                              : ((k2 > k3) ? k2 : k3);
                const unsigned m = __reduce_max_sync(FULL, lk);
                if (m < M4) break;              // pool no longer representative
                const unsigned bal = __ballot_sync(FULL, lk == m);
                const int src      = __ffs(bal) - 1;
                const int slot     = (k1 == m) ? 1 : ((k2 == m) ? 2 : 3);
                const unsigned cp  = (slot==1) ? pp1 : ((slot==2) ? pp2 : pp3);
                const float cx1 = (slot==1)?f1.x:((slot==2)?f2.x:f3.x);
                const float cy1 = (slot==1)?f1.y:((slot==2)?f2.y:f3.y);
                const float cx2 = (slot==1)?f1.z:((slot==2)?f2.z:f3.z);
                const float cy2 = (slot==1)?f1.w:((slot==2)?f2.w:f3.w);
                const unsigned psel = __shfl_sync(FULL, cp, src);
                const float sel = __uint_as_float(m);
                if (!(sel > THRESH)) {          // m >= M4 => true argmax
                    fz = 1; fp = psel; break;
                }
                const float mx1 = __shfl_sync(FULL, cx1, src);
                const float my1 = __shfl_sync(FULL, cy1, src);
                const float mx2 = __shfl_sync(FULL, cx2, src);
                const float my2 = __shfl_sync(FULL, cy2, src);
                const float mar = (mx2 - mx1) * (my2 - my1);
                if (lane == src) {
                    sbatch_box[B]  = make_float4(mx1, my1, mx2, my2);
                    sbatch_meta[B] = make_uint2(psel, m);
                    if ((NBOX + step + B) < out_size)
                        out[NBOX + step + B] = (float)g_orig[psel];
                    if (slot == 1) k1 = 0u; else if (slot == 2) k2 = 0u; else k3 = 0u;
                }
                __syncwarp();
                if (lane == 0) st_rel(&spub, B + 1);   // publish member B
                // decay pool entries (bit-identical to thread path, same order)
                if (k1 != 0u) {
                    const float iw = fmaxf(fminf(mx2, f1.z) - fmaxf(mx1, f1.x), 0.0f);
                    const float ih = fmaxf(fminf(my2, f1.w) - fmaxf(my1, f1.y), 0.0f);
                    const float inter = iw * ih;
                    if (inter > 0.0f) {
                        const float iou = __fdividef(inter, mar + a1 - inter);
                        k1 = __float_as_uint(__uint_as_float(k1) * __expf(-2.0f*iou*iou));
                    }
                }
                if (k2 != 0u) {
                    const float iw = fmaxf(fminf(mx2, f2.z) - fmaxf(mx1, f2.x), 0.0f);
                    const float ih = fmaxf(fminf(my2, f2.w) - fmaxf(my1, f2.y), 0.0f);
                    const float inter = iw * ih;
                    if (inter > 0.0f) {
                        const float iou = __fdividef(inter, mar + a2 - inter);
                        k2 = __float_as_uint(__uint_as_float(k2) * __expf(-2.0f*iou*iou));
                    }
                }
                if (k3 != 0u) {
                    const float iw = fmaxf(fminf(mx2, f3.z) - fmaxf(mx1, f3.x), 0.0f);
                    const float ih = fmaxf(fminf(my2, f3.w) - fmaxf(my1, f3.y), 0.0f);
                    const float inter = iw * ih;
                    if (inter > 0.0f) {
                        const float iou = __fdividef(inter, mar + a3 - inter);
                        k3 = __float_as_uint(__uint_as_float(k3) * __expf(-2.0f*iou*iou));
                    }
                }
                B++;
                if (B == BMAX) break;
            }
            if (lane == 0) { sfro = fz; sfpos = (int)fp; }
            __syncwarp();
            if (lane == 0) st_rel(&sdone, B);
            __syncwarp();
            // ---- producer applies the batch to its own slab ----
            for (int j = 0; j < B; j++) {
                const float4 mb = sbatch_box[j];
                const uint2  mm = sbatch_meta[j];
                if (mb.x <= tx2hi && mb.z >= tx1lo) {
                    const float mar = (mb.z - mb.x) * (mb.w - mb.y);
#pragma unroll
                    for (int k = 0; k < PER; k++) {
                        if ((procm >> k) & 1u) continue;
                        if (t * PER + k == (int)mm.x) {
                            procm |= 1u << k;
                            if (orig[k] < out_size) out[orig[k]] = __uint_as_float(mm.y);
                            dirty = true;
                        } else {
                            const float iw = fmaxf(fminf(mb.z, x2[k]) - fmaxf(mb.x, x1[k]), 0.0f);
                            const float ih = fmaxf(fminf(mb.w, y2[k]) - fmaxf(mb.y, y1[k]), 0.0f);
                            const float inter = iw * ih;
                            if (inter > 0.0f) {
                                const float iou = __fdividef(inter, mar + area[k] - inter);
                                s[k] *= __expf(-2.0f * iou * iou);
                                dirty = true;
                            }
                        }
                    }
                }
            }
        } else {
            // ============== consumers: drain-and-apply while scanning ======
            int applied = 0;
            while (true) {
                const int pub = ld_acq(&spub);
                while (applied < pub) {
                    const float4 mb = sbatch_box[applied];
                    const uint2  mm = sbatch_meta[applied];
                    if (mb.x <= tx2hi && mb.z >= tx1lo) {
                        const float mar = (mb.z - mb.x) * (mb.w - mb.y);
#pragma unroll
                        for (int k = 0; k < PER; k++) {
                            if ((procm >> k) & 1u) continue;
                            if (t * PER + k == (int)mm.x) {
                                procm |= 1u << k;
                                if (orig[k] < out_size) out[orig[k]] = __uint_as_float(mm.y);
                                dirty = true;
                            } else {
                                const float iw = fmaxf(fminf(mb.z, x2[k]) - fmaxf(mb.x, x1[k]), 0.0f);
                                const float ih = fmaxf(fminf(mb.w, y2[k]) - fmaxf(mb.y, y1[k]), 0.0f);
                                const float inter = iw * ih;
                                if (inter > 0.0f) {
                                    const float iou = __fdividef(inter, mar + area[k] - inter);
                                    s[k] *= __expf(-2.0f * iou * iou);
                                    dirty = true;
                                }
                            }
                        }
                    }
                    applied++;
                }
                const int dn = ld_acq(&sdone);
                if (dn >= 0 && applied >= dn) break;
                __nanosleep(40);
            }
        }
        __syncthreads();   // bar2: batch fully applied everywhere

        const int Bn = sdone;
        step += Bn;
        if (sfro) { fro_final = 1; fpos_final = sfpos; break; }
        // Bn == 0 without frozen is impossible: first candidate always >= M4
    }

    // ---- frozen tail: all remaining steps re-select the same argmax ----
    if (fro_final && step < NBOX) {
        const int fo = g_orig[fpos_final];
        for (int j = step + t; j < NBOX; j += T) {
            if ((NBOX + j) < out_size) out[NBOX + j] = (float)fo;
        }
    }
}

extern "C" void kernel_launch(void* const* d_in, const int* in_sizes, int n_in,
                              void* d_out, int out_size)
{
    const float4* boxes;
    const float*  scores;
    if (in_sizes[0] == 4 * NBOX) {
        boxes  = (const float4*)d_in[0];
        scores = (const float*)d_in[1];
    } else {
        boxes  = (const float4*)d_in[1];
        scores = (const float*)d_in[0];
    }
    softnms_kernel<<<1, T>>>(boxes, scores, (float*)d_out, out_size);
}

// round 9
// speedup vs baseline: 1.2485x; 1.2485x over previous
#include <cuda_runtime.h>

#define NBOX 4096
#define T 1024
#define PER 4                  // NBOX / T
#define NWARP 32
#define BMAX 64
#define THRESH 0.05f
#define FULL 0xffffffffu

__device__ float4 g_sbox[NBOX];
__device__ int    g_orig[NBOX];

__device__ __forceinline__ int ld_acq(const int* p) {
    int v;
    asm volatile("ld.acquire.cta.b32 %0, [%1];" : "=r"(v) : "l"(p) : "memory");
    return v;
}
__device__ __forceinline__ void st_rel(int* p, int v) {
    asm volatile("st.release.cta.b32 [%0], %1;" :: "l"(p), "r"(v) : "memory");
}

__global__ __launch_bounds__(T, 1)
void softnms_kernel(const float4* __restrict__ boxes,
                    const float*  __restrict__ scores,
                    float* __restrict__ out, int out_size)
{
    __shared__ unsigned long long skv[NBOX];   // sort scratch
    __shared__ uint4    spoolA[NWARP];         // (k1, p1, k2, p2) exact keys
    __shared__ unsigned sm3[NWARP];            // per-warp 3rd-best value
    __shared__ float4   sbatch_box[BMAX];
    __shared__ uint2    sbatch_meta[BMAX];     // (sorted pos, exact score bits)
    __shared__ int      spub, sdone, sfro, sfpos;

    const int t    = threadIdx.x;
    const int lane = t & 31;
    const int wid  = t >> 5;

    // ---- init: zero score outputs, stage u64 sort keys ----
#pragma unroll
    for (int k = 0; k < PER; k++) {
        const int gi = t * PER + k;
        if (gi < out_size) out[gi] = 0.0f;
        skv[gi] = ((unsigned long long)__float_as_uint(boxes[gi].x) << 32)
                  | (unsigned)gi;
    }
    __syncthreads();

    // ---- bitonic sort ascending by x1 ----
    for (int k = 2; k <= NBOX; k <<= 1) {
        for (int j = k >> 1; j > 0; j >>= 1) {
#pragma unroll
            for (int e = t; e < NBOX; e += T) {
                const int ixj = e ^ j;
                if (ixj > e) {
                    const unsigned long long a = skv[e], c = skv[ixj];
                    const bool up = ((e & k) == 0);
                    if (up ? (a > c) : (a < c)) { skv[e] = c; skv[ixj] = a; }
                }
            }
            __syncthreads();
        }
    }

    // ---- load my PER sorted boxes; publish sorted tables ----
    float x1[PER], y1[PER], x2[PER], y2[PER], area[PER], s[PER];
    int   orig[PER];
    unsigned procm = 0;
    float tx2hi = 0.0f;
#pragma unroll
    for (int k = 0; k < PER; k++) {
        const int pos = t * PER + k;
        const int o   = (int)(unsigned)(skv[pos] & 0xffffffffu);
        orig[k] = o;
        const float4 b = boxes[o];
        x1[k] = b.x; y1[k] = b.y; x2[k] = b.z; y2[k] = b.w;
        area[k] = (b.z - b.x) * (b.w - b.y);
        s[k]    = scores[o];
        g_sbox[pos] = b;
        g_orig[pos] = o;
        tx2hi = fmaxf(tx2hi, b.z);
    }
    const float tx1lo = x1[0];
    __syncthreads();

    bool dirty = true;
    int  step  = 0;
    int  fro_final = 0, fpos_final = 0;

    while (step < NBOX) {
        // ========= rebuild per-warp top-2 (+3rd value), EXACT argmax =======
        if (__ballot_sync(FULL, dirty)) {
            unsigned b1 = 0, b2 = 0, b3 = 0, p1 = 0, p2 = 0;
#pragma unroll
            for (int k = 0; k < PER; k++) {
                if (!((procm >> k) & 1u)) {
                    const unsigned ub = __float_as_uint(s[k]);   // scores > 0
                    const unsigned up = (unsigned)(t * PER + k);
                    if (ub > b1)      { b3 = b2; b2 = b1; p2 = p1; b1 = ub; p1 = up; }
                    else if (ub > b2) { b3 = b2; b2 = ub; p2 = up; }
                    else if (ub > b3) { b3 = ub; }
                }
            }
            const unsigned m1   = __reduce_max_sync(FULL, b1);
            const unsigned bal1 = __ballot_sync(FULL, b1 == m1);
            const int s1        = __ffs(bal1) - 1;
            const unsigned q1   = __shfl_sync(FULL, p1, s1);
            const unsigned v2   = (lane == s1) ? b2 : b1;
            const unsigned vp2  = (lane == s1) ? p2 : p1;
            const unsigned m2   = __reduce_max_sync(FULL, v2);
            const unsigned bal2 = __ballot_sync(FULL, v2 == m2);
            const int s2        = __ffs(bal2) - 1;
            const unsigned q2   = __shfl_sync(FULL, vp2, s2);
            unsigned v3 = b1;
            if (lane == s1) v3 = b2;
            if (lane == s2) v3 = (s2 == s1) ? b3 : b2;
            const unsigned m3 = __reduce_max_sync(FULL, v3);
            if (lane == 0) { spoolA[wid] = make_uint4(m1, q1, m2, q2); sm3[wid] = m3; }
            dirty = false;
        }
        if (t == 0) { spub = 0; sdone = -1; sfro = 0; }
        __syncthreads();   // bar1: pools + flags visible

        if (wid == 0) {
            // =========== producer: batch scan (decay-and-continue) =========
            const uint4 a = spoolA[lane];
            unsigned k1 = a.x, pp1 = a.y, k2 = a.z, pp2 = a.w;
            const unsigned M3 = __reduce_max_sync(FULL, sm3[lane]);
            float4 f1 = g_sbox[pp1]; const float a1 = (f1.z - f1.x) * (f1.w - f1.y);
            float4 f2 = g_sbox[pp2]; const float a2 = (f2.z - f2.x) * (f2.w - f2.y);

            int B = 0, fz = 0; unsigned fp = 0;
            while (true) {
                const bool s1w      = (k1 >= k2);
                const unsigned kmax = s1w ? k1 : k2;
                const unsigned m    = __reduce_max_sync(FULL, kmax);
                if (m < M3) break;                   // pool no longer covers order
                const unsigned bal = __ballot_sync(FULL, kmax == m);
                const int src      = __ffs(bal) - 1;
                const unsigned psel = __shfl_sync(FULL, s1w ? pp1 : pp2, src);
                if (!(__uint_as_float(m) > THRESH)) {  // pool max == global max
                    fz = 1; fp = psel; break;
                }
                const float mx1 = __shfl_sync(FULL, s1w ? f1.x : f2.x, src);
                const float my1 = __shfl_sync(FULL, s1w ? f1.y : f2.y, src);
                const float mx2 = __shfl_sync(FULL, s1w ? f1.z : f2.z, src);
                const float my2 = __shfl_sync(FULL, s1w ? f1.w : f2.w, src);
                const float mar = (mx2 - mx1) * (my2 - my1);
                if (lane == src) {
                    sbatch_box[B]  = make_float4(mx1, my1, mx2, my2);
                    sbatch_meta[B] = make_uint2(psel, m);
                    if ((NBOX + step + B) < out_size)
                        out[NBOX + step + B] = (float)g_orig[psel];
                    if (s1w) k1 = 0u; else k2 = 0u;   // consume
                }
                __syncwarp();
                if (lane == 0) st_rel(&spub, B + 1);  // stream member B out
                // decay surviving pool entries (bit-identical to thread path)
                if (k1 != 0u) {
                    const float iw = fmaxf(fminf(mx2, f1.z) - fmaxf(mx1, f1.x), 0.0f);
                    const float ih = fmaxf(fminf(my2, f1.w) - fmaxf(my1, f1.y), 0.0f);
                    const float inter = iw * ih;
                    if (inter > 0.0f) {
                        const float iou = __fdividef(inter, mar + a1 - inter);
                        k1 = __float_as_uint(__uint_as_float(k1) * __expf(-2.0f * iou * iou));
                    }
                }
                if (k2 != 0u) {
                    const float iw = fmaxf(fminf(mx2, f2.z) - fmaxf(mx1, f2.x), 0.0f);
                    const float ih = fmaxf(fminf(my2, f2.w) - fmaxf(my1, f2.y), 0.0f);
                    const float inter = iw * ih;
                    if (inter > 0.0f) {
                        const float iou = __fdividef(inter, mar + a2 - inter);
                        k2 = __float_as_uint(__uint_as_float(k2) * __expf(-2.0f * iou * iou));
                    }
                }
                B++;
                if (B == BMAX) break;
            }
            if (lane == 0) { sfro = fz; sfpos = (int)fp; }
            __syncwarp();
            if (lane == 0) st_rel(&sdone, B);
            // ---- producer applies the batch to its own slab ----
            for (int j = 0; j < B; j++) {
                const float4 mb = sbatch_box[j];
                const uint2  mm = sbatch_meta[j];
                if (mb.x <= tx2hi && mb.z >= tx1lo) {
                    const float mar = (mb.z - mb.x) * (mb.w - mb.y);
#pragma unroll
                    for (int k = 0; k < PER; k++) {
                        if ((procm >> k) & 1u) continue;
                        if (t * PER + k == (int)mm.x) {
                            procm |= 1u << k;
                            if (orig[k] < out_size) out[orig[k]] = __uint_as_float(mm.y);
                            dirty = true;
                        } else {
                            const float iw = fmaxf(fminf(mb.z, x2[k]) - fmaxf(mb.x, x1[k]), 0.0f);
                            const float ih = fmaxf(fminf(mb.w, y2[k]) - fmaxf(mb.y, y1[k]), 0.0f);
                            const float inter = iw * ih;
                            if (inter > 0.0f) {
                                const float iou = __fdividef(inter, mar + area[k] - inter);
                                s[k] *= __expf(-2.0f * iou * iou);
                                dirty = true;
                            }
                        }
                    }
                }
            }
        } else {
            // ======= consumers: stream-apply members as they publish =======
            int applied = 0;
            while (true) {
                const int pub = ld_acq(&spub);
                while (applied < pub) {
                    const float4 mb = sbatch_box[applied];
                    const uint2  mm = sbatch_meta[applied];
                    if (mb.x <= tx2hi && mb.z >= tx1lo) {
                        const float mar = (mb.z - mb.x) * (mb.w - mb.y);
#pragma unroll
                        for (int k = 0; k < PER; k++) {
                            if ((procm >> k) & 1u) continue;
                            if (t * PER + k == (int)mm.x) {
                                procm |= 1u << k;
                                if (orig[k] < out_size) out[orig[k]] = __uint_as_float(mm.y);
                                dirty = true;
                            } else {
                                const float iw = fmaxf(fminf(mb.z, x2[k]) - fmaxf(mb.x, x1[k]), 0.0f);
                                const float ih = fmaxf(fminf(mb.w, y2[k]) - fmaxf(mb.y, y1[k]), 0.0f);
                                const float inter = iw * ih;
                                if (inter > 0.0f) {
                                    const float iou = __fdividef(inter, mar + area[k] - inter);
                                    s[k] *= __expf(-2.0f * iou * iou);
                                    dirty = true;
                                }
                            }
                        }
                    }
                    applied++;
                }
                const int dn = ld_acq(&sdone);
                if (dn >= 0 && applied >= dn) break;
                __nanosleep(60);
            }
        }
        __syncthreads();   // bar2: batch fully applied everywhere

        step += sdone;
        if (sfro) { fro_final = 1; fpos_final = sfpos; break; }
    }

    // ---- frozen tail: all remaining steps re-select the same argmax ----
    if (fro_final && step < NBOX) {
        const int fo = g_orig[fpos_final];
        for (int j = step + t; j < NBOX; j += T) {
            if ((NBOX + j) < out_size) out[NBOX + j] = (float)fo;
        }
    }
}

extern "C" void kernel_launch(void* const* d_in, const int* in_sizes, int n_in,
                              void* d_out, int out_size)
{
    const float4* boxes;
    const float*  scores;
    if (in_sizes[0] == 4 * NBOX) {
        boxes  = (const float4*)d_in[0];
        scores = (const float*)d_in[1];
    } else {
        boxes  = (const float4*)d_in[1];
        scores = (const float*)d_in[0];
    }
    softnms_kernel<<<1, T>>>(boxes, scores, (float*)d_out, out_size);
}

// round 10
// speedup vs baseline: 1.3526x; 1.0834x over previous
#include <cuda_runtime.h>

#define NBOX 4096
#define T 1024
#define PER 4                  // NBOX / T
#define NWARP 32
#define BMAX 64
#define THRESH 0.05f
#define FULL 0xffffffffu

__device__ float4 g_sbox[NBOX];
__device__ int    g_orig[NBOX];

__device__ __forceinline__ int ld_acq(const int* p) {
    int v;
    asm volatile("ld.acquire.cta.b32 %0, [%1];" : "=r"(v) : "l"(p) : "memory");
    return v;
}
__device__ __forceinline__ void st_rel(int* p, int v) {
    asm volatile("st.release.cta.b32 [%0], %1;" :: "l"(p), "r"(v) : "memory");
}

__global__ __launch_bounds__(T, 1)
void softnms_kernel(const float4* __restrict__ boxes,
                    const float*  __restrict__ scores,
                    float* __restrict__ out, int out_size)
{
    __shared__ unsigned long long skv[NBOX];   // sort scratch
    __shared__ uint4    spoolA[NWARP];         // (k1, p1, k2, p2) exact keys
    __shared__ unsigned sm3[NWARP];            // per-warp 3rd-best value
    __shared__ float4   sbatch_box[BMAX];
    __shared__ uint2    sbatch_meta[BMAX];     // (sorted pos, exact score bits)
    __shared__ int      spub, sdone;           // sdone: B | fz<<8 | fp<<9

    const int t    = threadIdx.x;
    const int lane = t & 31;
    const int wid  = t >> 5;

    // ---- init: zero score outputs, stage u64 sort keys ----
#pragma unroll
    for (int k = 0; k < PER; k++) {
        const int gi = t * PER + k;
        if (gi < out_size) out[gi] = 0.0f;
        skv[gi] = ((unsigned long long)__float_as_uint(boxes[gi].x) << 32)
                  | (unsigned)gi;
    }
    __syncthreads();

    // ---- bitonic sort ascending by x1 ----
    for (int k = 2; k <= NBOX; k <<= 1) {
        for (int j = k >> 1; j > 0; j >>= 1) {
#pragma unroll
            for (int e = t; e < NBOX; e += T) {
                const int ixj = e ^ j;
                if (ixj > e) {
                    const unsigned long long a = skv[e], c = skv[ixj];
                    const bool up = ((e & k) == 0);
                    if (up ? (a > c) : (a < c)) { skv[e] = c; skv[ixj] = a; }
                }
            }
            __syncthreads();
        }
    }

    // ---- load my PER sorted boxes; publish sorted tables ----
    float x1[PER], y1[PER], x2[PER], y2[PER], area[PER], s[PER];
    int   orig[PER];
    unsigned procm = 0;
    float tx2hi = 0.0f;
#pragma unroll
    for (int k = 0; k < PER; k++) {
        const int pos = t * PER + k;
        const int o   = (int)(unsigned)(skv[pos] & 0xffffffffu);
        orig[k] = o;
        const float4 b = boxes[o];
        x1[k] = b.x; y1[k] = b.y; x2[k] = b.z; y2[k] = b.w;
        area[k] = (b.z - b.x) * (b.w - b.y);
        s[k]    = scores[o];
        g_sbox[pos] = b;
        g_orig[pos] = o;
        tx2hi = fmaxf(tx2hi, b.z);
    }
    const float tx1lo = x1[0];
    __syncthreads();

    bool dirty = true;
    int  step  = 0;
    int  fro_final = 0, fpos_final = 0;

    while (step < NBOX) {
        // ========= rebuild per-warp top-2 (+3rd value), EXACT argmax =======
        if (__ballot_sync(FULL, dirty)) {
            unsigned b1 = 0, b2 = 0, b3 = 0, p1 = 0, p2 = 0;
#pragma unroll
            for (int k = 0; k < PER; k++) {
                if (!((procm >> k) & 1u)) {
                    const unsigned ub = __float_as_uint(s[k]);   // scores > 0
                    const unsigned up = (unsigned)(t * PER + k);
                    if (ub > b1)      { b3 = b2; b2 = b1; p2 = p1; b1 = ub; p1 = up; }
                    else if (ub > b2) { b3 = b2; b2 = ub; p2 = up; }
                    else if (ub > b3) { b3 = ub; }
                }
            }
            const unsigned m1   = __reduce_max_sync(FULL, b1);
            const unsigned bal1 = __ballot_sync(FULL, b1 == m1);
            const int s1        = __ffs(bal1) - 1;
            const unsigned q1   = __shfl_sync(FULL, p1, s1);
            const unsigned v2   = (lane == s1) ? b2 : b1;
            const unsigned vp2  = (lane == s1) ? p2 : p1;
            const unsigned m2   = __reduce_max_sync(FULL, v2);
            const unsigned bal2 = __ballot_sync(FULL, v2 == m2);
            const int s2        = __ffs(bal2) - 1;
            const unsigned q2   = __shfl_sync(FULL, vp2, s2);
            unsigned v3 = b1;
            if (lane == s1) v3 = b2;
            if (lane == s2) v3 = (s2 == s1) ? b3 : b2;
            const unsigned m3 = __reduce_max_sync(FULL, v3);
            if (lane == 0) { spoolA[wid] = make_uint4(m1, q1, m2, q2); sm3[wid] = m3; }
            dirty = false;
        }
        if (t == 0) { spub = 0; sdone = -1; }
        __syncthreads();   // bar1: pools + flags visible

        if (wid == 0) {
            // ===== producer: branchless batch scan (decay-and-continue) ====
            const uint4 a = spoolA[lane];
            unsigned k1 = a.x, pp1 = a.y, k2 = a.z, pp2 = a.w;
            const unsigned M3 = __reduce_max_sync(FULL, sm3[lane]);
            const float4 f1 = g_sbox[pp1]; const float a1 = (f1.z - f1.x) * (f1.w - f1.y);
            const float4 f2 = g_sbox[pp2]; const float a2 = (f2.z - f2.x) * (f2.w - f2.y);
            const int og1 = g_orig[pp1];
            const int og2 = g_orig[pp2];

            int B = 0, fz = 0; unsigned fp = 0;
            while (true) {
                const bool s1w      = (k1 >= k2);
                const unsigned kmax = s1w ? k1 : k2;
                const unsigned m    = __reduce_max_sync(FULL, kmax);
                if (m < M3) break;                   // pool no longer covers order
                const unsigned bal = __ballot_sync(FULL, kmax == m);
                const int src      = __ffs(bal) - 1;
                const unsigned psel = __shfl_sync(FULL, s1w ? pp1 : pp2, src);
                if (!(__uint_as_float(m) > THRESH)) {  // pool max == global max
                    fz = 1; fp = psel; break;
                }
                const float mx1 = __shfl_sync(FULL, s1w ? f1.x : f2.x, src);
                const float my1 = __shfl_sync(FULL, s1w ? f1.y : f2.y, src);
                const float mx2 = __shfl_sync(FULL, s1w ? f1.z : f2.z, src);
                const float my2 = __shfl_sync(FULL, s1w ? f1.w : f2.w, src);
                const float mar = (mx2 - mx1) * (my2 - my1);
                const bool is_src = (lane == src);
                if (is_src) {                        // predicated stores
                    sbatch_box[B]  = make_float4(mx1, my1, mx2, my2);
                    sbatch_meta[B] = make_uint2(psel, m);
                    if ((NBOX + step + B) < out_size)
                        out[NBOX + step + B] = (float)(s1w ? og1 : og2);
                    st_rel(&spub, B + 1);            // src's release orders its stores
                }
                // predicated consume (0 stays 0 through later decays)
                k1 = (is_src &&  s1w) ? 0u : k1;
                k2 = (is_src && !s1w) ? 0u : k2;
                // unconditional bit-exact decay (inter==0 -> multiply by 1.0f)
                {
                    const float iw = fmaxf(fminf(mx2, f1.z) - fmaxf(mx1, f1.x), 0.0f);
                    const float ih = fmaxf(fminf(my2, f1.w) - fmaxf(my1, f1.y), 0.0f);
                    const float inter = iw * ih;
                    const float iou = __fdividef(inter, mar + a1 - inter);
                    k1 = __float_as_uint(__uint_as_float(k1) * __expf(-2.0f * iou * iou));
                }
                {
                    const float iw = fmaxf(fminf(mx2, f2.z) - fmaxf(mx1, f2.x), 0.0f);
                    const float ih = fmaxf(fminf(my2, f2.w) - fmaxf(my1, f2.y), 0.0f);
                    const float inter = iw * ih;
                    const float iou = __fdividef(inter, mar + a2 - inter);
                    k2 = __float_as_uint(__uint_as_float(k2) * __expf(-2.0f * iou * iou));
                }
                B++;
                if (B == BMAX) break;
            }
            __syncwarp();                            // fence all lanes' stores
            if (lane == 0)
                st_rel(&sdone, B | (fz << 8) | ((int)fp << 9));
            // ---- producer applies the batch to its own slab ----
            for (int j = 0; j < B; j++) {
                const float4 mb = sbatch_box[j];
                const uint2  mm = sbatch_meta[j];
                if (mb.x <= tx2hi && mb.z >= tx1lo) {
                    const float mar = (mb.z - mb.x) * (mb.w - mb.y);
#pragma unroll
                    for (int k = 0; k < PER; k++) {
                        if ((procm >> k) & 1u) continue;
                        if (t * PER + k == (int)mm.x) {
                            procm |= 1u << k;
                            if (orig[k] < out_size) out[orig[k]] = __uint_as_float(mm.y);
                            dirty = true;
                        } else {
                            const float iw = fmaxf(fminf(mb.z, x2[k]) - fmaxf(mb.x, x1[k]), 0.0f);
                            const float ih = fmaxf(fminf(mb.w, y2[k]) - fmaxf(mb.y, y1[k]), 0.0f);
                            const float inter = iw * ih;
                            if (inter > 0.0f) {
                                const float iou = __fdividef(inter, mar + area[k] - inter);
                                s[k] *= __expf(-2.0f * iou * iou);
                                dirty = true;
                            }
                        }
                    }
                }
            }
        } else {
            // ======= consumers: stream-apply members as they publish =======
            int applied = 0;
            while (true) {
                const int pub = ld_acq(&spub);
                while (applied < pub) {
                    const float4 mb = sbatch_box[applied];
                    const uint2  mm = sbatch_meta[applied];
                    if (mb.x <= tx2hi && mb.z >= tx1lo) {
                        const float mar = (mb.z - mb.x) * (mb.w - mb.y);
#pragma unroll
                        for (int k = 0; k < PER; k++) {
                            if ((procm >> k) & 1u) continue;
                            if (t * PER + k == (int)mm.x) {
                                procm |= 1u << k;
                                if (orig[k] < out_size) out[orig[k]] = __uint_as_float(mm.y);
                                dirty = true;
                            } else {
                                const float iw = fmaxf(fminf(mb.z, x2[k]) - fmaxf(mb.x, x1[k]), 0.0f);
                                const float ih = fmaxf(fminf(mb.w, y2[k]) - fmaxf(mb.y, y1[k]), 0.0f);
                                const float inter = iw * ih;
                                if (inter > 0.0f) {
                                    const float iou = __fdividef(inter, mar + area[k] - inter);
                                    s[k] *= __expf(-2.0f * iou * iou);
                                    dirty = true;
                                }
                            }
                        }
                    }
                    applied++;
                }
                const int dn = ld_acq(&sdone);
                if (dn >= 0 && applied >= (dn & 0xff)) break;
                __nanosleep(80);
            }
        }
        __syncthreads();   // bar2: batch fully applied everywhere

        const int dn = sdone;
        step += (dn & 0xff);
        if (dn & 0x100) { fro_final = 1; fpos_final = dn >> 9; break; }
    }

    // ---- frozen tail: all remaining steps re-select the same argmax ----
    if (fro_final && step < NBOX) {
        const int fo = g_orig[fpos_final];
        for (int j = step + t; j < NBOX; j += T) {
            if ((NBOX + j) < out_size) out[NBOX + j] = (float)fo;
        }
    }
}

extern "C" void kernel_launch(void* const* d_in, const int* in_sizes, int n_in,
                              void* d_out, int out_size)
{
    const float4* boxes;
    const float*  scores;
    if (in_sizes[0] == 4 * NBOX) {
        boxes  = (const float4*)d_in[0];
        scores = (const float*)d_in[1];
    } else {
        boxes  = (const float4*)d_in[1];
        scores = (const float*)d_in[0];
    }
    softnms_kernel<<<1, T>>>(boxes, scores, (float*)d_out, out_size);
}

// round 11
// speedup vs baseline: 1.4720x; 1.0883x over previous
#include <cuda_runtime.h>

#define NBOX 4096
#define T 1024
#define PER 4                  // NBOX / T
#define NWARP 32
#define PROD (NWARP - 1)       // producer = HIGHEST wid (hi-wid-first arbiter)
#define BMAX 64
#define THRESH 0.05f
#define FULL 0xffffffffu

__device__ float4 g_sbox[NBOX];
__device__ int    g_orig[NBOX];

__device__ __forceinline__ int ld_acq(const int* p) {
    int v;
    asm volatile("ld.acquire.cta.b32 %0, [%1];" : "=r"(v) : "l"(p) : "memory");
    return v;
}
__device__ __forceinline__ void st_rel(int* p, int v) {
    asm volatile("st.release.cta.b32 [%0], %1;" :: "l"(p), "r"(v) : "memory");
}

__global__ __launch_bounds__(T, 1)
void softnms_kernel(const float4* __restrict__ boxes,
                    const float*  __restrict__ scores,
                    float* __restrict__ out, int out_size)
{
    __shared__ unsigned long long skv[NBOX];   // sort scratch
    __shared__ uint4    spoolA[NWARP];         // (k1, p1, k2, p2) exact keys
    __shared__ unsigned sm3[NWARP];            // per-warp 3rd-best value
    __shared__ float4   sbatch_box[BMAX];
    __shared__ uint2    sbatch_meta[BMAX];     // (sorted pos, exact score bits)
    __shared__ int      spub, sdone;           // sdone: B | fz<<8 | fp<<9

    const int t    = threadIdx.x;
    const int lane = t & 31;
    const int wid  = t >> 5;

    // ---- init: zero score outputs, stage u64 sort keys ----
#pragma unroll
    for (int k = 0; k < PER; k++) {
        const int gi = t * PER + k;
        if (gi < out_size) out[gi] = 0.0f;
        skv[gi] = ((unsigned long long)__float_as_uint(boxes[gi].x) << 32)
                  | (unsigned)gi;
    }
    __syncthreads();

    // ---- bitonic sort ascending by x1 ----
    for (int k = 2; k <= NBOX; k <<= 1) {
        for (int j = k >> 1; j > 0; j >>= 1) {
#pragma unroll
            for (int e = t; e < NBOX; e += T) {
                const int ixj = e ^ j;
                if (ixj > e) {
                    const unsigned long long a = skv[e], c = skv[ixj];
                    const bool up = ((e & k) == 0);
                    if (up ? (a > c) : (a < c)) { skv[e] = c; skv[ixj] = a; }
                }
            }
            __syncthreads();
        }
    }

    // ---- load my PER sorted boxes; publish sorted tables ----
    float x1[PER], y1[PER], x2[PER], y2[PER], area[PER], s[PER];
    int   orig[PER];
    unsigned procm = 0;
    float tx2hi = 0.0f;
#pragma unroll
    for (int k = 0; k < PER; k++) {
        const int pos = t * PER + k;
        const int o   = (int)(unsigned)(skv[pos] & 0xffffffffu);
        orig[k] = o;
        const float4 b = boxes[o];
        x1[k] = b.x; y1[k] = b.y; x2[k] = b.z; y2[k] = b.w;
        area[k] = (b.z - b.x) * (b.w - b.y);
        s[k]    = scores[o];
        g_sbox[pos] = b;
        g_orig[pos] = o;
        tx2hi = fmaxf(tx2hi, b.z);
    }
    const float tx1lo = x1[0];
    __syncthreads();

    bool dirty = true;
    int  step  = 0;
    int  fro_final = 0, fpos_final = 0;

    while (step < NBOX) {
        // ========= rebuild per-warp top-2 (+3rd value), EXACT argmax =======
        if (__ballot_sync(FULL, dirty)) {
            unsigned b1 = 0, b2 = 0, b3 = 0, p1 = 0, p2 = 0;
#pragma unroll
            for (int k = 0; k < PER; k++) {
                if (!((procm >> k) & 1u)) {
                    const unsigned ub = __float_as_uint(s[k]);   // scores > 0
                    const unsigned up = (unsigned)(t * PER + k);
                    if (ub > b1)      { b3 = b2; b2 = b1; p2 = p1; b1 = ub; p1 = up; }
                    else if (ub > b2) { b3 = b2; b2 = ub; p2 = up; }
                    else if (ub > b3) { b3 = ub; }
                }
            }
            const unsigned m1   = __reduce_max_sync(FULL, b1);
            const unsigned bal1 = __ballot_sync(FULL, b1 == m1);
            const int s1        = __ffs(bal1) - 1;
            const unsigned q1   = __shfl_sync(FULL, p1, s1);
            const unsigned v2   = (lane == s1) ? b2 : b1;
            const unsigned vp2  = (lane == s1) ? p2 : p1;
            const unsigned m2   = __reduce_max_sync(FULL, v2);
            const unsigned bal2 = __ballot_sync(FULL, v2 == m2);
            const int s2        = __ffs(bal2) - 1;
            const unsigned q2   = __shfl_sync(FULL, vp2, s2);
            unsigned v3 = b1;
            if (lane == s1) v3 = b2;
            if (lane == s2) v3 = (s2 == s1) ? b3 : b2;
            const unsigned m3 = __reduce_max_sync(FULL, v3);
            if (lane == 0) { spoolA[wid] = make_uint4(m1, q1, m2, q2); sm3[wid] = m3; }
            dirty = false;
        }
        if (t == 0) { spub = 0; sdone = -1; }
        __syncthreads();   // bar1: pools + flags visible

        if (wid == PROD) {
            // ===== producer (highest-wid warp): branchless batch scan ======
            const uint4 a = spoolA[lane];
            unsigned k1 = a.x, pp1 = a.y, k2 = a.z, pp2 = a.w;
            const unsigned M3 = __reduce_max_sync(FULL, sm3[lane]);
            const float4 f1 = g_sbox[pp1]; const float a1 = (f1.z - f1.x) * (f1.w - f1.y);
            const float4 f2 = g_sbox[pp2]; const float a2 = (f2.z - f2.x) * (f2.w - f2.y);

            int B = 0, fz = 0; unsigned fp = 0;
            while (true) {
                const bool s1w      = (k1 >= k2);
                const unsigned kmax = s1w ? k1 : k2;
                const unsigned m    = __reduce_max_sync(FULL, kmax);
                if (m < M3) break;                   // pool no longer covers order
                const unsigned bal = __ballot_sync(FULL, kmax == m);
                const int src      = __ffs(bal) - 1;
                if (!(__uint_as_float(m) > THRESH)) {  // pool max == global max
                    fz = 1;
                    fp = __shfl_sync(FULL, s1w ? pp1 : pp2, src);  // rare path
                    break;
                }
                const float mx1 = __shfl_sync(FULL, s1w ? f1.x : f2.x, src);
                const float my1 = __shfl_sync(FULL, s1w ? f1.y : f2.y, src);
                const float mx2 = __shfl_sync(FULL, s1w ? f1.z : f2.z, src);
                const float my2 = __shfl_sync(FULL, s1w ? f1.w : f2.w, src);
                const float mar = (mx2 - mx1) * (my2 - my1);
                const bool is_src = (lane == src);
                if (is_src) {                        // src-lane publishes member
                    sbatch_box[B]  = make_float4(mx1, my1, mx2, my2);
                    sbatch_meta[B] = make_uint2(s1w ? pp1 : pp2, m);
                    st_rel(&spub, B + 1);            // orders src's own stores
                }
                // predicated consume (0 stays 0 through later decays)
                k1 = (is_src &&  s1w) ? 0u : k1;
                k2 = (is_src && !s1w) ? 0u : k2;
                // unconditional bit-exact decay (inter==0 -> multiply by 1.0f)
                {
                    const float iw = fmaxf(fminf(mx2, f1.z) - fmaxf(mx1, f1.x), 0.0f);
                    const float ih = fmaxf(fminf(my2, f1.w) - fmaxf(my1, f1.y), 0.0f);
                    const float inter = iw * ih;
                    const float iou = __fdividef(inter, mar + a1 - inter);
                    k1 = __float_as_uint(__uint_as_float(k1) * __expf(-2.0f * iou * iou));
                }
                {
                    const float iw = fmaxf(fminf(mx2, f2.z) - fmaxf(mx1, f2.x), 0.0f);
                    const float ih = fmaxf(fminf(my2, f2.w) - fmaxf(my1, f2.y), 0.0f);
                    const float inter = iw * ih;
                    const float iou = __fdividef(inter, mar + a2 - inter);
                    k2 = __float_as_uint(__uint_as_float(k2) * __expf(-2.0f * iou * iou));
                }
                B++;
                if (B == BMAX) break;
            }
            __syncwarp();                            // fence all lanes' stores
            if (lane == 0)
                st_rel(&sdone, B | (fz << 8) | ((int)fp << 9));
            // ---- producer applies the batch to its own slab ----
            for (int j = 0; j < B; j++) {
                const float4 mb = sbatch_box[j];
                const uint2  mm = sbatch_meta[j];
                if (mb.x <= tx2hi && mb.z >= tx1lo) {
                    const float mar = (mb.z - mb.x) * (mb.w - mb.y);
#pragma unroll
                    for (int k = 0; k < PER; k++) {
                        if ((procm >> k) & 1u) continue;
                        if (t * PER + k == (int)mm.x) {
                            procm |= 1u << k;
                            if (orig[k] < out_size) out[orig[k]] = __uint_as_float(mm.y);
                            dirty = true;
                        } else {
                            const float iw = fmaxf(fminf(mb.z, x2[k]) - fmaxf(mb.x, x1[k]), 0.0f);
                            const float ih = fmaxf(fminf(mb.w, y2[k]) - fmaxf(mb.y, y1[k]), 0.0f);
                            const float inter = iw * ih;
                            if (inter > 0.0f) {
                                const float iou = __fdividef(inter, mar + area[k] - inter);
                                s[k] *= __expf(-2.0f * iou * iou);
                                dirty = true;
                            }
                        }
                    }
                }
            }
        } else {
            // ======= consumers: stream-apply members as they publish =======
            int applied = 0;
            while (true) {
                const int pub = ld_acq(&spub);
                while (applied < pub) {
                    const float4 mb = sbatch_box[applied];
                    const uint2  mm = sbatch_meta[applied];
                    // thread 0 records the idxs output (off the scan chain)
                    if (t == 0 && (NBOX + step + applied) < out_size)
                        out[NBOX + step + applied] = (float)g_orig[mm.x];
                    if (mb.x <= tx2hi && mb.z >= tx1lo) {
                        const float mar = (mb.z - mb.x) * (mb.w - mb.y);
#pragma unroll
                        for (int k = 0; k < PER; k++) {
                            if ((procm >> k) & 1u) continue;
                            if (t * PER + k == (int)mm.x) {
                                procm |= 1u << k;
                                if (orig[k] < out_size) out[orig[k]] = __uint_as_float(mm.y);
                                dirty = true;
                            } else {
                                const float iw = fmaxf(fminf(mb.z, x2[k]) - fmaxf(mb.x, x1[k]), 0.0f);
                                const float ih = fmaxf(fminf(mb.w, y2[k]) - fmaxf(mb.y, y1[k]), 0.0f);
                                const float inter = iw * ih;
                                if (inter > 0.0f) {
                                    const float iou = __fdividef(inter, mar + area[k] - inter);
                                    s[k] *= __expf(-2.0f * iou * iou);
                                    dirty = true;
                                }
                            }
                        }
                    }
                    applied++;
                }
                const int dn = ld_acq(&sdone);
                if (dn >= 0 && applied >= (dn & 0xff)) break;
                __nanosleep(100);
            }
        }
        __syncthreads();   // bar2: batch fully applied everywhere

        const int dn = sdone;
        step += (dn & 0xff);
        if (dn & 0x100) { fro_final = 1; fpos_final = dn >> 9; break; }
    }

    // ---- frozen tail: all remaining steps re-select the same argmax ----
    if (fro_final && step < NBOX) {
        const int fo = g_orig[fpos_final];
        for (int j = step + t; j < NBOX; j += T) {
            if ((NBOX + j) < out_size) out[NBOX + j] = (float)fo;
        }
    }
}

extern "C" void kernel_launch(void* const* d_in, const int* in_sizes, int n_in,
                              void* d_out, int out_size)
{
    const float4* boxes;
    const float*  scores;
    if (in_sizes[0] == 4 * NBOX) {
        boxes  = (const float4*)d_in[0];
        scores = (const float*)d_in[1];
    } else {
        boxes  = (const float4*)d_in[1];
        scores = (const float*)d_in[0];
    }
    softnms_kernel<<<1, T>>>(boxes, scores, (float*)d_out, out_size);
}